// round 11
// baseline (speedup 1.0000x reference)
#include <cuda_runtime.h>
#include <cuda_fp16.h>
#include <cstdint>

// out[b][o] = sum_k x[b][k] * W[o][k] + bias[o]
// x: (1048576,128) f32, W: (128,128) f32, bias: (128,1), out f32.
//
// R10: R9 (169.8us) + 3-stage x pipeline. LDG for tile i+2 issues at the END
// of tile i's mainloop and stays in flight across epilogue+barrier (DRAM read
// stream no longer goes dark during the write phase); STS for tile i+1 lands
// at ks=0/2 of tile i from registers loaded a full tile earlier (latency
// fully covered). 3 bufs remove the WAR hazard. Everything else unchanged:
// permuted-W STG.128 epilogue, 2 CTAs/SM, warp tile 32x32, rel_err 2.9e-4.

#define THREADS 256
#define KDIM    128
#define TILE_B  64

// smem: x tiles [buf0..2] 16KB at 0/16K/32K; W at 48K..80K
#define XS_OFF(b)  ((b)*16384)
#define WS_OFF     49152
#define SMEM_BYTES 81920

// ---------------- helpers ----------------
__device__ __forceinline__ uint32_t smem_u32(const void* p) {
    uint32_t a;
    asm("{ .reg .u64 t; cvta.to.shared.u64 t, %1; cvt.u32.u64 %0, t; }" : "=r"(a) : "l"(p));
    return a;
}
__device__ __forceinline__ void sts64(uint32_t addr, uint32_t a, uint32_t b) {
    asm volatile("st.shared.v2.b32 [%0], {%1,%2};" :: "r"(addr), "r"(a), "r"(b));
}
__device__ __forceinline__ void ldsm4(uint32_t r[4], uint32_t addr) {
    asm volatile("ldmatrix.sync.aligned.m8n8.x4.shared.b16 {%0,%1,%2,%3}, [%4];"
                 : "=r"(r[0]), "=r"(r[1]), "=r"(r[2]), "=r"(r[3]) : "r"(addr));
}
__device__ __forceinline__ void hmma(float* d, const uint32_t a[4], uint32_t b0, uint32_t b1) {
    asm volatile("mma.sync.aligned.m16n8k16.row.col.f32.f16.f16.f32 "
                 "{%0,%1,%2,%3}, {%4,%5,%6,%7}, {%8,%9}, {%0,%1,%2,%3};"
                 : "+f"(d[0]), "+f"(d[1]), "+f"(d[2]), "+f"(d[3])
                 : "r"(a[0]), "r"(a[1]), "r"(a[2]), "r"(a[3]), "r"(b0), "r"(b1));
}
__device__ __forceinline__ uint32_t cvt_h2(float xx, float yy) {
    __half2 h = __float22half2_rn(make_float2(xx, yy));
    return *reinterpret_cast<uint32_t*>(&h);
}
// fp16 tile swizzle: rows x 256B, XOR on 16B granules
__device__ __forceinline__ uint32_t swz(int row, uint32_t kb) {
    return (uint32_t)row * 256u + (kb ^ (uint32_t)((row & 7) << 4));
}
// o-permutation: physical output col o -> smem B-tile row pn (see R9).
__device__ __forceinline__ int operm(int o) {
    const int ng_ = o >> 5;
    const int pr_ = (o >> 4) & 1;
    const int t_  = (o >> 2) & 3;
    const int p_  = (o >> 1) & 1;
    const int u_  = o & 1;
    return ng_ * 32 + (pr_ * 2 + p_) * 8 + t_ * 2 + u_;
}

// ---- staging: 64 rows x 128 f32 = 2048 float4; 4 per thread per batch, 2 batches ----
__device__ __forceinline__ void ldg_batch(const float4* __restrict__ src, int tid, int j,
                                          float4 st[4]) {
    #pragma unroll
    for (int it = 0; it < 4; ++it) st[it] = src[tid + (j * 4 + it) * THREADS];
}
__device__ __forceinline__ void sts_batch(uint32_t xs, int tid, int j, const float4 st[4]) {
    #pragma unroll
    for (int it = 0; it < 4; ++it) {
        int fidx = tid + (j * 4 + it) * THREADS;   // float4 index in 64x32
        int row = fidx >> 5;
        int g4  = fidx & 31;
        uint32_t off = swz(row, (uint32_t)(g4 * 8));
        sts64(xs + off, cvt_h2(st[it].x, st[it].y), cvt_h2(st[it].z, st[it].w));
    }
}

__global__ __launch_bounds__(THREADS, 2)
void linear128_f16_kernel(const float* __restrict__ x,
                          const float* __restrict__ W,
                          const float* __restrict__ bias,
                          float* __restrict__ out,
                          int ntiles)
{
    extern __shared__ __align__(1024) char smem[];
    const uint32_t sb = smem_u32(smem);
    const uint32_t ws = sb + WS_OFF;

    const int tid  = threadIdx.x;
    const int lane = tid & 31;
    const int wid  = tid >> 5;
    const int mg   = wid >> 2;   // 0..1: batch rows 32*mg
    const int ng   = wid & 3;    // 0..3: out cols 32*ng

    // ---- stage W (fp16) into smem with o-permutation, once ----
    {
        const float4* W4 = (const float4*)W;
        #pragma unroll
        for (int it = 0; it < 16; ++it) {
            int fidx = tid + it * THREADS;
            int o   = fidx >> 5;
            int g4  = fidx & 31;
            float4 v = W4[fidx];
            int pn = operm(o);
            sts64(ws + swz(pn, (uint32_t)(g4 * 8)),
                  cvt_h2(v.x, v.y), cvt_h2(v.z, v.w));
        }
    }

    // ---- bias: one float4 per fragment pair ----
    float4 bv[2];
    #pragma unroll
    for (int pr = 0; pr < 2; ++pr)
        bv[pr] = *(const float4*)(bias + ng * 32 + pr * 16 + (lane & 3) * 4);

    // ---- ldmatrix address components ----
    uint32_t a_ro[2], a_sw[2];
    #pragma unroll
    for (int mf = 0; mf < 2; ++mf) {
        int r = mg * 32 + mf * 16 + ((lane >> 3) & 1) * 8 + (lane & 7);
        a_ro[mf] = (uint32_t)r * 256u;
        a_sw[mf] = (uint32_t)((r & 7) << 4);
    }
    const uint32_t a_kb = (uint32_t)((lane >> 4) * 16);
    uint32_t b_ro[2], b_sw[2];
    #pragma unroll
    for (int q = 0; q < 2; ++q) {
        int r = ng * 32 + q * 16 + ((lane >> 4) << 3) + (lane & 7);
        b_ro[q] = (uint32_t)r * 256u;
        b_sw[q] = (uint32_t)((r & 7) << 4);
    }
    const uint32_t b_kb = (uint32_t)(((lane >> 3) & 1) * 16);

    const int bid  = blockIdx.x;
    const int grid = gridDim.x;
    const float4* x4 = (const float4*)x;

    float4 st0[4], st1[4];   // held LDG data for the NEXT tile (live across sync)

    // ---- prologue: stage tile(bid) into buf0; LDG tile(bid+grid) into regs ----
    {
        float4 st[4];
        ldg_batch(x4 + (size_t)bid * 2048, tid, 0, st);
        sts_batch(sb + XS_OFF(0), tid, 0, st);
        ldg_batch(x4 + (size_t)bid * 2048, tid, 1, st);
        sts_batch(sb + XS_OFF(0), tid, 1, st);
        if (bid + grid < ntiles) {
            ldg_batch(x4 + (size_t)(bid + grid) * 2048, tid, 0, st0);
            ldg_batch(x4 + (size_t)(bid + grid) * 2048, tid, 1, st1);
        }
    }
    __syncthreads();

    int i = 0;
    #pragma unroll 1
    for (int tile = bid; tile < ntiles; tile += grid, ++i) {
        // buffer indices mod 3
        const int cb = i % 3;
        const int nb = (i + 1) % 3;
        const uint32_t xs  = sb + XS_OFF(cb);
        const uint32_t nxs = sb + XS_OFF(nb);
        const bool hn1 = (tile + grid)     < ntiles;   // tile i+1 exists
        const bool hn2 = (tile + 2 * grid) < ntiles;   // tile i+2 exists
        const float4* n2src = x4 + (size_t)(tile + 2 * grid) * 2048;

        float d[2][4][4];
        #pragma unroll
        for (int mf = 0; mf < 2; ++mf)
            #pragma unroll
            for (int nf = 0; nf < 4; ++nf)
                #pragma unroll
                for (int e = 0; e < 4; ++e) d[mf][nf][e] = 0.0f;

        #pragma unroll
        for (int ks = 0; ks < 8; ++ks) {
            const uint32_t kbyte = (uint32_t)(ks * 32);
            uint32_t a[2][4];
            #pragma unroll
            for (int mf = 0; mf < 2; ++mf)
                ldsm4(a[mf], xs + a_ro[mf] + ((kbyte + a_kb) ^ a_sw[mf]));
            uint32_t b0[4], b1[4];
            #pragma unroll
            for (int q = 0; q < 2; ++q) {
                uint32_t r[4];
                ldsm4(r, ws + b_ro[q] + ((kbyte + b_kb) ^ b_sw[q]));
                b0[2*q] = r[0]; b1[2*q] = r[1]; b0[2*q+1] = r[2]; b1[2*q+1] = r[3];
            }
            #pragma unroll
            for (int mf = 0; mf < 2; ++mf)
                #pragma unroll
                for (int nf = 0; nf < 4; ++nf)
                    hmma(d[mf][nf], a[mf], b0[nf], b1[nf]);

            // STS of tile i+1 (regs LDG'd a full tile ago -> latency covered)
            if (ks == 0 && hn1) { sts_batch(nxs, tid, 0, st0); }
            if (ks == 2 && hn1) { sts_batch(nxs, tid, 1, st1); }
            // LDG of tile i+2: stays in flight across epilogue + barrier
            if (ks == 5 && hn2) { ldg_batch(n2src, tid, 0, st0); }
            if (ks == 7 && hn2) { ldg_batch(n2src, tid, 1, st1); }
        }

        // ---- epilogue: STG.128, 4 consecutive phys cols per thread ----
        #pragma unroll
        for (int mf = 0; mf < 2; ++mf) {
            const size_t rbase =
                ((size_t)tile * TILE_B + (size_t)(mg * 32 + mf * 16 + (lane >> 2))) * 128;
            #pragma unroll
            for (int pr = 0; pr < 2; ++pr) {
                const int col = ng * 32 + pr * 16 + (lane & 3) * 4;
                float4 v0, v1;
                v0.x = d[mf][2*pr][0]   + bv[pr].x;
                v0.y = d[mf][2*pr][1]   + bv[pr].y;
                v0.z = d[mf][2*pr+1][0] + bv[pr].z;
                v0.w = d[mf][2*pr+1][1] + bv[pr].w;
                v1.x = d[mf][2*pr][2]   + bv[pr].x;
                v1.y = d[mf][2*pr][3]   + bv[pr].y;
                v1.z = d[mf][2*pr+1][2] + bv[pr].z;
                v1.w = d[mf][2*pr+1][3] + bv[pr].w;
                *(float4*)(out + rbase + col)           = v0;
                *(float4*)(out + rbase + 8 * 128 + col) = v1;
            }
        }
        __syncthreads();   // buf(i) reads done; buf(i+1) staging visible
    }
}

extern "C" void kernel_launch(void* const* d_in, const int* in_sizes, int n_in,
                              void* d_out, int out_size)
{
    const float* x    = (const float*)d_in[0];
    const float* W    = (const float*)d_in[1];
    const float* bias = (const float*)d_in[2];
    float* out = (float*)d_out;

    const int batch  = in_sizes[0] / KDIM;   // 1048576
    const int ntiles = batch / TILE_B;       // 16384

    int sms = 148;
    cudaDeviceGetAttribute(&sms, cudaDevAttrMultiProcessorCount, 0);
    if (sms <= 0) sms = 148;
    int grid = 2 * sms;                      // 2 CTAs per SM
    if (grid > ntiles) grid = ntiles;

    cudaFuncSetAttribute(linear128_f16_kernel,
                         cudaFuncAttributeMaxDynamicSharedMemorySize, SMEM_BYTES);

    linear128_f16_kernel<<<grid, THREADS, SMEM_BYTES>>>(x, W, bias, out, ntiles);
}

// round 12
// speedup vs baseline: 1.0500x; 1.0500x over previous
#include <cuda_runtime.h>
#include <cuda_fp16.h>
#include <cstdint>

// out[b][o] = sum_k x[b][k] * W[o][k] + bias[o]
// x: (1048576,128) f32, W: (128,128) f32, bias: (128,1), out f32.
//
// R11 = R9 (169.8us best: fp16 mma, 2 CTAs/SM, permuted-W STG.128 epilogue)
//  + streaming cache hints (__ldcs for x, __stcs for out: both touched once)
//  + longer LDG in-flight window (LDG b1 at ks0, STS at ks4/6; was ks1,3/5).
// R10's 3-buf pipeline regressed (regs 128, fma up) and is reverted.
// Register liveness across the barrier is unchanged vs R9.

#define THREADS 256
#define KDIM    128
#define TILE_B  64

// smem: x tiles [buf] 16KB at 0/16K; W at 32K..64K
#define XS_OFF(b)  ((b)*16384)
#define WS_OFF     32768
#define SMEM_BYTES 65536

// ---------------- helpers ----------------
__device__ __forceinline__ uint32_t smem_u32(const void* p) {
    uint32_t a;
    asm("{ .reg .u64 t; cvta.to.shared.u64 t, %1; cvt.u32.u64 %0, t; }" : "=r"(a) : "l"(p));
    return a;
}
__device__ __forceinline__ void sts64(uint32_t addr, uint32_t a, uint32_t b) {
    asm volatile("st.shared.v2.b32 [%0], {%1,%2};" :: "r"(addr), "r"(a), "r"(b));
}
__device__ __forceinline__ void ldsm4(uint32_t r[4], uint32_t addr) {
    asm volatile("ldmatrix.sync.aligned.m8n8.x4.shared.b16 {%0,%1,%2,%3}, [%4];"
                 : "=r"(r[0]), "=r"(r[1]), "=r"(r[2]), "=r"(r[3]) : "r"(addr));
}
__device__ __forceinline__ void hmma(float* d, const uint32_t a[4], uint32_t b0, uint32_t b1) {
    asm volatile("mma.sync.aligned.m16n8k16.row.col.f32.f16.f16.f32 "
                 "{%0,%1,%2,%3}, {%4,%5,%6,%7}, {%8,%9}, {%0,%1,%2,%3};"
                 : "+f"(d[0]), "+f"(d[1]), "+f"(d[2]), "+f"(d[3])
                 : "r"(a[0]), "r"(a[1]), "r"(a[2]), "r"(a[3]), "r"(b0), "r"(b1));
}
__device__ __forceinline__ uint32_t cvt_h2(float xx, float yy) {
    __half2 h = __float22half2_rn(make_float2(xx, yy));
    return *reinterpret_cast<uint32_t*>(&h);
}
// fp16 tile swizzle: rows x 256B, XOR on 16B granules
__device__ __forceinline__ uint32_t swz(int row, uint32_t kb) {
    return (uint32_t)row * 256u + (kb ^ (uint32_t)((row & 7) << 4));
}
// o-permutation: physical output col o -> smem B-tile row pn (see R9).
__device__ __forceinline__ int operm(int o) {
    const int ng_ = o >> 5;
    const int pr_ = (o >> 4) & 1;
    const int t_  = (o >> 2) & 3;
    const int p_  = (o >> 1) & 1;
    const int u_  = o & 1;
    return ng_ * 32 + (pr_ * 2 + p_) * 8 + t_ * 2 + u_;
}

// ---- staging: 64 rows x 128 f32 = 2048 float4; 4 per thread per batch ----
__device__ __forceinline__ void ldg_batch(const float4* __restrict__ src, int tid, int j,
                                          float4 st[4]) {
    #pragma unroll
    for (int it = 0; it < 4; ++it) st[it] = __ldcs(src + tid + (j * 4 + it) * THREADS);
}
__device__ __forceinline__ void sts_batch(uint32_t xs, int tid, int j, const float4 st[4]) {
    #pragma unroll
    for (int it = 0; it < 4; ++it) {
        int fidx = tid + (j * 4 + it) * THREADS;   // float4 index in 64x32
        int row = fidx >> 5;
        int g4  = fidx & 31;
        uint32_t off = swz(row, (uint32_t)(g4 * 8));
        sts64(xs + off, cvt_h2(st[it].x, st[it].y), cvt_h2(st[it].z, st[it].w));
    }
}

__global__ __launch_bounds__(THREADS, 2)
void linear128_f16_kernel(const float* __restrict__ x,
                          const float* __restrict__ W,
                          const float* __restrict__ bias,
                          float* __restrict__ out,
                          int ntiles)
{
    extern __shared__ __align__(1024) char smem[];
    const uint32_t sb = smem_u32(smem);
    const uint32_t ws = sb + WS_OFF;

    const int tid  = threadIdx.x;
    const int lane = tid & 31;
    const int wid  = tid >> 5;
    const int mg   = wid >> 2;   // 0..1: batch rows 32*mg
    const int ng   = wid & 3;    // 0..3: out cols 32*ng

    // ---- stage W (fp16) into smem with o-permutation, once ----
    {
        const float4* W4 = (const float4*)W;
        #pragma unroll
        for (int it = 0; it < 16; ++it) {
            int fidx = tid + it * THREADS;
            int o   = fidx >> 5;
            int g4  = fidx & 31;
            float4 v = W4[fidx];
            int pn = operm(o);
            sts64(ws + swz(pn, (uint32_t)(g4 * 8)),
                  cvt_h2(v.x, v.y), cvt_h2(v.z, v.w));
        }
    }

    // ---- bias: one float4 per fragment pair ----
    float4 bv[2];
    #pragma unroll
    for (int pr = 0; pr < 2; ++pr)
        bv[pr] = *(const float4*)(bias + ng * 32 + pr * 16 + (lane & 3) * 4);

    // ---- ldmatrix address components ----
    uint32_t a_ro[2], a_sw[2];
    #pragma unroll
    for (int mf = 0; mf < 2; ++mf) {
        int r = mg * 32 + mf * 16 + ((lane >> 3) & 1) * 8 + (lane & 7);
        a_ro[mf] = (uint32_t)r * 256u;
        a_sw[mf] = (uint32_t)((r & 7) << 4);
    }
    const uint32_t a_kb = (uint32_t)((lane >> 4) * 16);
    uint32_t b_ro[2], b_sw[2];
    #pragma unroll
    for (int q = 0; q < 2; ++q) {
        int r = ng * 32 + q * 16 + ((lane >> 4) << 3) + (lane & 7);
        b_ro[q] = (uint32_t)r * 256u;
        b_sw[q] = (uint32_t)((r & 7) << 4);
    }
    const uint32_t b_kb = (uint32_t)(((lane >> 3) & 1) * 16);

    const int bid  = blockIdx.x;
    const int grid = gridDim.x;
    const float4* x4 = (const float4*)x;

    // ---- prologue: stage x tile(bid) into buf 0 ----
    {
        float4 st[4];
        ldg_batch(x4 + (size_t)bid * 2048, tid, 0, st);
        sts_batch(sb + XS_OFF(0), tid, 0, st);
        ldg_batch(x4 + (size_t)bid * 2048, tid, 1, st);
        sts_batch(sb + XS_OFF(0), tid, 1, st);
    }
    __syncthreads();

    int i = 0;
    #pragma unroll 1
    for (int tile = bid; tile < ntiles; tile += grid, ++i) {
        const uint32_t xs  = sb + XS_OFF(i & 1);
        const uint32_t nxs = sb + XS_OFF((i + 1) & 1);
        const bool hn = (tile + grid) < ntiles;
        const float4* nsrc = x4 + (size_t)(tile + grid) * 2048;

        float d[2][4][4];
        #pragma unroll
        for (int mf = 0; mf < 2; ++mf)
            #pragma unroll
            for (int nf = 0; nf < 4; ++nf)
                #pragma unroll
                for (int e = 0; e < 4; ++e) d[mf][nf][e] = 0.0f;

        float4 st0[4], st1[4];
        if (hn) ldg_batch(nsrc, tid, 0, st0);   // issue reads ASAP after barrier

        #pragma unroll
        for (int ks = 0; ks < 8; ++ks) {
            const uint32_t kbyte = (uint32_t)(ks * 32);
            uint32_t a[2][4];
            #pragma unroll
            for (int mf = 0; mf < 2; ++mf)
                ldsm4(a[mf], xs + a_ro[mf] + ((kbyte + a_kb) ^ a_sw[mf]));
            uint32_t b0[4], b1[4];
            #pragma unroll
            for (int q = 0; q < 2; ++q) {
                uint32_t r[4];
                ldsm4(r, ws + b_ro[q] + ((kbyte + b_kb) ^ b_sw[q]));
                b0[2*q] = r[0]; b1[2*q] = r[1]; b0[2*q+1] = r[2]; b1[2*q+1] = r[3];
            }
            #pragma unroll
            for (int mf = 0; mf < 2; ++mf)
                #pragma unroll
                for (int nf = 0; nf < 4; ++nf)
                    hmma(d[mf][nf], a[mf], b0[nf], b1[nf]);

            // reads outstanding over most of the mainloop; STS late
            if (ks == 0 && hn) { ldg_batch(nsrc, tid, 1, st1); }
            if (ks == 4 && hn) { sts_batch(nxs, tid, 0, st0); }
            if (ks == 6 && hn) { sts_batch(nxs, tid, 1, st1); }
        }

        // ---- epilogue: streaming STG.128, 4 consecutive phys cols/thread ----
        #pragma unroll
        for (int mf = 0; mf < 2; ++mf) {
            const size_t rbase =
                ((size_t)tile * TILE_B + (size_t)(mg * 32 + mf * 16 + (lane >> 2))) * 128;
            #pragma unroll
            for (int pr = 0; pr < 2; ++pr) {
                const int col = ng * 32 + pr * 16 + (lane & 3) * 4;
                float4 v0, v1;
                v0.x = d[mf][2*pr][0]   + bv[pr].x;
                v0.y = d[mf][2*pr][1]   + bv[pr].y;
                v0.z = d[mf][2*pr+1][0] + bv[pr].z;
                v0.w = d[mf][2*pr+1][1] + bv[pr].w;
                v1.x = d[mf][2*pr][2]   + bv[pr].x;
                v1.y = d[mf][2*pr][3]   + bv[pr].y;
                v1.z = d[mf][2*pr+1][2] + bv[pr].z;
                v1.w = d[mf][2*pr+1][3] + bv[pr].w;
                __stcs((float4*)(out + rbase + col),           v0);
                __stcs((float4*)(out + rbase + 8 * 128 + col), v1);
            }
        }
        __syncthreads();   // buf(i) reads done; buf(i+1) staging visible
    }
}

extern "C" void kernel_launch(void* const* d_in, const int* in_sizes, int n_in,
                              void* d_out, int out_size)
{
    const float* x    = (const float*)d_in[0];
    const float* W    = (const float*)d_in[1];
    const float* bias = (const float*)d_in[2];
    float* out = (float*)d_out;

    const int batch  = in_sizes[0] / KDIM;   // 1048576
    const int ntiles = batch / TILE_B;       // 16384

    int sms = 148;
    cudaDeviceGetAttribute(&sms, cudaDevAttrMultiProcessorCount, 0);
    if (sms <= 0) sms = 148;
    int grid = 2 * sms;                      // 2 CTAs per SM
    if (grid > ntiles) grid = ntiles;

    cudaFuncSetAttribute(linear128_f16_kernel,
                         cudaFuncAttributeMaxDynamicSharedMemorySize, SMEM_BYTES);

    linear128_f16_kernel<<<grid, THREADS, SMEM_BYTES>>>(x, W, bias, out, ntiles);
}